// round 3
// baseline (speedup 1.0000x reference)
#include <cuda_runtime.h>
#include <cuda_bf16.h>
#include <math.h>
#include <stdint.h>

// Problem constants (fixed shapes)
#define DIMV    2048
#define NHEADS  32
#define NKV     8
#define HD      64
#define BATCH   2
#define SEQ     1024
#define MROWS   (BATCH*SEQ)          // 2048
#define KVDIM   (NKV*HD)             // 512

// -------- scratch (no allocations allowed) --------
__device__ float g_q[(size_t)MROWS * DIMV];
__device__ float g_k[(size_t)MROWS * KVDIM];
__device__ float g_v[(size_t)MROWS * KVDIM];
__device__ float g_attn[(size_t)MROWS * DIMV];

// ============================================================
// TF32 tensor-core GEMM: C[M,N] = A[M,K] @ B[K,N], fp32 in/out.
// BM=BN=128, BK=16, 256 threads (8 warps, 4x2), warp tile 32x64.
// mma.sync.aligned.m16n8k8.row.col.f32.tf32.tf32.f32
// A smem: row-major, row stride 20 floats  (conflict-free frags)
// B smem: [k][n], stride 128, col ^= 8*(k&3) (conflict-free frags)
// Double-buffered; cvt.rna.tf32 on the load path.
// Requires M%128==0, N%128==0, K%16==0.
// ============================================================
#define BM 128
#define BN 128
#define BK 16
#define ASTR 20

__device__ __forceinline__ uint32_t f2tf32(float x) {
    uint32_t u;
    asm("cvt.rna.tf32.f32 %0, %1;" : "=r"(u) : "f"(x));
    return u;
}

__device__ __forceinline__ void mma_tf32(float* d, const uint32_t* a, const uint32_t* b) {
    asm volatile(
        "mma.sync.aligned.m16n8k8.row.col.f32.tf32.tf32.f32 "
        "{%0,%1,%2,%3}, {%4,%5,%6,%7}, {%8,%9}, {%0,%1,%2,%3};\n"
        : "+f"(d[0]), "+f"(d[1]), "+f"(d[2]), "+f"(d[3])
        : "r"(a[0]), "r"(a[1]), "r"(a[2]), "r"(a[3]),
          "r"(b[0]), "r"(b[1]));
}

__global__ __launch_bounds__(256) void tgemm_kernel(
    const float* __restrict__ A, const float* __restrict__ B,
    float* __restrict__ C, int M, int N, int K)
{
    __shared__ uint32_t As[2][BM * ASTR];     // tf32 bits
    __shared__ uint32_t Bs[2][BK * BN];

    const int tid  = threadIdx.x;
    const int wid  = tid >> 5;
    const int lane = tid & 31;
    const int g    = lane >> 2;    // groupID 0..7
    const int t    = lane & 3;     // threadID-in-group 0..3
    const int m0   = blockIdx.y * BM;
    const int n0   = blockIdx.x * BN;
    const int mrow = (wid & 3) * 32;   // warp row base within tile
    const int ncol = (wid >> 2) * 64;  // warp col base within tile

    // Loader coords (2 float4 per thread per tile)
    const int ar0 = tid >> 2,          ac0 = (tid & 3) * 4;
    const int ar1 = (tid + 256) >> 2,  ac1 = ((tid + 256) & 3) * 4;
    const int br0 = tid >> 5,          bn0 = (tid & 31) * 4;
    const int br1 = (tid + 256) >> 5,  bn1 = bn0;
    const int bs0 = bn0 ^ (8 * (br0 & 3));   // swizzled store col
    const int bs1 = bn1 ^ (8 * (br1 & 3));

    const float* Ag0 = A + (size_t)(m0 + ar0) * K + ac0;
    const float* Ag1 = A + (size_t)(m0 + ar1) * K + ac1;
    const float* Bg0 = B + (size_t)br0 * N + n0 + bn0;
    const float* Bg1 = B + (size_t)br1 * N + n0 + bn1;

    float acc[2][8][4];
#pragma unroll
    for (int mt = 0; mt < 2; mt++)
#pragma unroll
        for (int nt = 0; nt < 8; nt++)
#pragma unroll
            for (int r = 0; r < 4; r++) acc[mt][nt][r] = 0.f;

    // --- commit helper expanded inline: preload tile 0 ---
    {
        float4 a0 = *(const float4*)(Ag0);
        float4 a1 = *(const float4*)(Ag1);
        float4 b0 = *(const float4*)(Bg0);
        float4 b1 = *(const float4*)(Bg1);
        uint32_t* Asm = As[0];
        Asm[ar0*ASTR + ac0+0] = f2tf32(a0.x); Asm[ar0*ASTR + ac0+1] = f2tf32(a0.y);
        Asm[ar0*ASTR + ac0+2] = f2tf32(a0.z); Asm[ar0*ASTR + ac0+3] = f2tf32(a0.w);
        Asm[ar1*ASTR + ac1+0] = f2tf32(a1.x); Asm[ar1*ASTR + ac1+1] = f2tf32(a1.y);
        Asm[ar1*ASTR + ac1+2] = f2tf32(a1.z); Asm[ar1*ASTR + ac1+3] = f2tf32(a1.w);
        uint32_t* Bsm = Bs[0];
        uint4 bb0 = make_uint4(f2tf32(b0.x), f2tf32(b0.y), f2tf32(b0.z), f2tf32(b0.w));
        uint4 bb1 = make_uint4(f2tf32(b1.x), f2tf32(b1.y), f2tf32(b1.z), f2tf32(b1.w));
        *(uint4*)(&Bsm[br0*BN + bs0]) = bb0;
        *(uint4*)(&Bsm[br1*BN + bs1]) = bb1;
    }
    __syncthreads();

    const int niter = K / BK;
    for (int it = 0; it < niter; it++) {
        const int cur = it & 1, nxt = cur ^ 1;

        // prefetch next tile into registers
        float4 pa0, pa1, pb0, pb1;
        const bool has_next = (it + 1) < niter;
        if (has_next) {
            const int ko = (it + 1) * BK;
            pa0 = *(const float4*)(Ag0 + ko);
            pa1 = *(const float4*)(Ag1 + ko);
            pb0 = *(const float4*)(Bg0 + (size_t)ko * N);
            pb1 = *(const float4*)(Bg1 + (size_t)ko * N);
        }

        // compute on current buffer: 2 k-steps of 8
        const uint32_t* Asm = As[cur];
        const uint32_t* Bsm = Bs[cur];
#pragma unroll
        for (int s = 0; s < 2; s++) {
            const int k0 = s * 8;
            uint32_t afr[2][4];
#pragma unroll
            for (int mt = 0; mt < 2; mt++) {
                const int rb = mrow + mt * 16;
                afr[mt][0] = Asm[(rb + g    ) * ASTR + k0 + t    ];
                afr[mt][1] = Asm[(rb + g + 8) * ASTR + k0 + t    ];
                afr[mt][2] = Asm[(rb + g    ) * ASTR + k0 + t + 4];
                afr[mt][3] = Asm[(rb + g + 8) * ASTR + k0 + t + 4];
            }
            uint32_t bfr[8][2];
            const int swz = 8 * t;       // (k&3)*8 with k = k0+t, k0 in {0,8}
#pragma unroll
            for (int nt = 0; nt < 8; nt++) {
                const int col = (ncol + nt * 8 + g) ^ swz;
                bfr[nt][0] = Bsm[(k0 + t    ) * BN + col];
                bfr[nt][1] = Bsm[(k0 + t + 4) * BN + col];
            }
#pragma unroll
            for (int mt = 0; mt < 2; mt++)
#pragma unroll
                for (int nt = 0; nt < 8; nt++)
                    mma_tf32(acc[mt][nt], afr[mt], bfr[nt]);
        }

        // commit prefetched tile to the other buffer
        if (has_next) {
            uint32_t* Asn = As[nxt];
            Asn[ar0*ASTR + ac0+0] = f2tf32(pa0.x); Asn[ar0*ASTR + ac0+1] = f2tf32(pa0.y);
            Asn[ar0*ASTR + ac0+2] = f2tf32(pa0.z); Asn[ar0*ASTR + ac0+3] = f2tf32(pa0.w);
            Asn[ar1*ASTR + ac1+0] = f2tf32(pa1.x); Asn[ar1*ASTR + ac1+1] = f2tf32(pa1.y);
            Asn[ar1*ASTR + ac1+2] = f2tf32(pa1.z); Asn[ar1*ASTR + ac1+3] = f2tf32(pa1.w);
            uint32_t* Bsn = Bs[nxt];
            uint4 bb0 = make_uint4(f2tf32(pb0.x), f2tf32(pb0.y), f2tf32(pb0.z), f2tf32(pb0.w));
            uint4 bb1 = make_uint4(f2tf32(pb1.x), f2tf32(pb1.y), f2tf32(pb1.z), f2tf32(pb1.w));
            *(uint4*)(&Bsn[br0*BN + bs0]) = bb0;
            *(uint4*)(&Bsn[br1*BN + bs1]) = bb1;
            __syncthreads();
        }
    }

    // writeback: c0,c1 at (row, 2t), (row, 2t+1); c2,c3 at row+8
#pragma unroll
    for (int mt = 0; mt < 2; mt++) {
#pragma unroll
        for (int nt = 0; nt < 8; nt++) {
            const int row = m0 + mrow + mt * 16 + g;
            const int col = n0 + ncol + nt * 8 + 2 * t;
            float2 lo = make_float2(acc[mt][nt][0], acc[mt][nt][1]);
            float2 hi = make_float2(acc[mt][nt][2], acc[mt][nt][3]);
            *(float2*)(C + (size_t)row * N + col)       = lo;
            *(float2*)(C + (size_t)(row + 8) * N + col) = hi;
        }
    }
}

// ============================================================
// RoPE (in-place, interleaved pairs), matches fp32 reference math.
// ============================================================
__global__ void rope_kernel(float* __restrict__ t, int width, int npairs)
{
    int idx = blockIdx.x * blockDim.x + threadIdx.x;
    if (idx >= npairs) return;
    int ppr  = width >> 1;
    int row  = idx / ppr;
    int p    = idx - row * ppr;
    int i    = p & 31;                       // pair index within head
    int col  = ((p >> 5) << 6) + (i << 1);   // head*64 + 2*i
    int n    = row & (SEQ - 1);

    float freq  = powf(10000.0f, -(float)i * (1.0f / 32.0f));
    float phase = (float)n * freq;
    float s, c;
    sincosf(phase, &s, &c);

    float* base = t + (size_t)row * width + col;
    float x0 = base[0];
    float x1 = base[1];
    base[0] = x0 * c - x1 * s;
    base[1] = x0 * s + x1 * c;
}

// ============================================================
// Flash attention (causal, GQA rep=4), fp32.
// grid = (SEQ/128, B*H), block = 128. Thread t owns one query row.
// ============================================================
__global__ __launch_bounds__(128) void flash_kernel()
{
    __shared__ float4 Ksh[32 * 16];   // 32 keys x 64 floats
    __shared__ float4 Vsh[32 * 16];

    const int t  = threadIdx.x;
    const int qt = blockIdx.x;                 // 0..7
    const int bh = blockIdx.y;                 // 0..63
    const int b  = bh >> 5;
    const int h  = bh & 31;
    const int qi = qt * 128 + t;
    const int kvh = h >> 2;                    // GQA rep=4

    const float scale = 0.125f * 1.4426950408889634f;  // 1/sqrt(64) * log2(e)

    float4 q4[16];
    const float4* qp = (const float4*)(g_q + (size_t)(b * SEQ + qi) * DIMV + h * HD);
#pragma unroll
    for (int dd = 0; dd < 16; dd++) {
        float4 v = qp[dd];
        v.x *= scale; v.y *= scale; v.z *= scale; v.w *= scale;
        q4[dd] = v;
    }

    float m = -INFINITY, l = 0.f;
    float4 acc[16];
#pragma unroll
    for (int dd = 0; dd < 16; dd++) acc[dd] = make_float4(0.f, 0.f, 0.f, 0.f);

    const int ntiles = qt * 4 + 4;
    for (int kt = 0; kt < ntiles; kt++) {
#pragma unroll
        for (int u = 0; u < 4; u++) {
            int f  = t + u * 128;
            int j  = f >> 4;
            int dd = f & 15;
            size_t base = (size_t)(b * SEQ + kt * 32 + j) * KVDIM + kvh * HD;
            Ksh[f] = *(const float4*)(g_k + base + dd * 4);
            Vsh[f] = *(const float4*)(g_v + base + dd * 4);
        }
        __syncthreads();

        int jmax = qi - kt * 32 + 1;
        if (jmax > 32) jmax = 32;
        if (jmax > 0) {
            float sv[32];
#pragma unroll
            for (int j = 0; j < 32; j++) {
                float s = 0.f;
#pragma unroll
                for (int dd = 0; dd < 16; dd++) {
                    float4 kk = Ksh[j * 16 + dd];
                    s = fmaf(q4[dd].x, kk.x, s);
                    s = fmaf(q4[dd].y, kk.y, s);
                    s = fmaf(q4[dd].z, kk.z, s);
                    s = fmaf(q4[dd].w, kk.w, s);
                }
                sv[j] = (j < jmax) ? s : -INFINITY;
            }
            float tm = -INFINITY;
#pragma unroll
            for (int j = 0; j < 32; j++) tm = fmaxf(tm, sv[j]);
            float nm   = fmaxf(m, tm);
            float corr = exp2f(m - nm);
            l *= corr;
#pragma unroll
            for (int dd = 0; dd < 16; dd++) {
                acc[dd].x *= corr; acc[dd].y *= corr;
                acc[dd].z *= corr; acc[dd].w *= corr;
            }
#pragma unroll
            for (int j = 0; j < 32; j++) {
                float p = exp2f(sv[j] - nm);
                l += p;
#pragma unroll
                for (int dd = 0; dd < 16; dd++) {
                    float4 vv = Vsh[j * 16 + dd];
                    acc[dd].x = fmaf(p, vv.x, acc[dd].x);
                    acc[dd].y = fmaf(p, vv.y, acc[dd].y);
                    acc[dd].z = fmaf(p, vv.z, acc[dd].z);
                    acc[dd].w = fmaf(p, vv.w, acc[dd].w);
                }
            }
            m = nm;
        }
        __syncthreads();
    }

    float inv = 1.0f / l;
    float4* op = (float4*)(g_attn + (size_t)(b * SEQ + qi) * DIMV + h * HD);
#pragma unroll
    for (int dd = 0; dd < 16; dd++) {
        float4 v = acc[dd];
        v.x *= inv; v.y *= inv; v.z *= inv; v.w *= inv;
        op[dd] = v;
    }
}

// ============================================================
// Launch
// ============================================================
extern "C" void kernel_launch(void* const* d_in, const int* in_sizes, int n_in,
                              void* d_out, int out_size)
{
    const float* x  = (const float*)d_in[0];
    const float* wq = (const float*)d_in[1];
    const float* wk = (const float*)d_in[2];
    const float* wv = (const float*)d_in[3];
    const float* wo = (const float*)d_in[4];
    float* out = (float*)d_out;

    float *pq, *pk, *pv, *pa;
    cudaGetSymbolAddress((void**)&pq, g_q);
    cudaGetSymbolAddress((void**)&pk, g_k);
    cudaGetSymbolAddress((void**)&pv, g_v);
    cudaGetSymbolAddress((void**)&pa, g_attn);

    dim3 blk(256);
    // q = x @ wq   [2048,2048]
    tgemm_kernel<<<dim3(DIMV / BN, MROWS / BM), blk>>>(x, wq, pq, MROWS, DIMV, DIMV);
    // k = x @ wk   [2048,512]
    tgemm_kernel<<<dim3(KVDIM / BN, MROWS / BM), blk>>>(x, wk, pk, MROWS, KVDIM, DIMV);
    // v = x @ wv   [2048,512]
    tgemm_kernel<<<dim3(KVDIM / BN, MROWS / BM), blk>>>(x, wv, pv, MROWS, KVDIM, DIMV);

    // RoPE in-place on q and k
    {
        int npq = MROWS * (DIMV / 2);
        rope_kernel<<<(npq + 255) / 256, 256>>>(pq, DIMV, npq);
        int npk = MROWS * (KVDIM / 2);
        rope_kernel<<<(npk + 255) / 256, 256>>>(pk, KVDIM, npk);
    }

    // causal GQA attention -> g_attn [B*N, 2048]
    flash_kernel<<<dim3(SEQ / 128, BATCH * NHEADS), dim3(128)>>>();

    // out = attn @ wo  [2048,2048]
    tgemm_kernel<<<dim3(DIMV / BN, MROWS / BM), blk>>>(pa, wo, out, MROWS, DIMV, DIMV);
}

// round 11
// speedup vs baseline: 1.2388x; 1.2388x over previous
#include <cuda_runtime.h>
#include <cuda_bf16.h>
#include <math.h>
#include <stdint.h>

// Problem constants (fixed shapes)
#define DIMV    2048
#define NHEADS  32
#define NKV     8
#define HD      64
#define BATCH   2
#define SEQ     1024
#define MROWS   (BATCH*SEQ)          // 2048
#define KVDIM   (NKV*HD)             // 512
#define QKVW    (DIMV + 2*KVDIM)     // 3072 fused width

typedef unsigned long long u64;

// -------- scratch (no allocations allowed) --------
__device__ float g_qkv[(size_t)MROWS * QKVW];     // [row][ q(2048) | k(512) | v(512) ]
__device__ float g_attn[(size_t)MROWS * DIMV];
__device__ float g_wf[(size_t)DIMV * QKVW];       // fused [K][3072] = [wq|wk|wv]

// ---- packed f32x2 helpers (sm_100+ base ISA, not 'a'-gated) ----
#define FMA2(d, a, b) asm("fma.rn.f32x2 %0, %1, %2, %0;" : "+l"(d) : "l"(a), "l"(b))
#define MUL2(d, a, b) asm("mul.rn.f32x2 %0, %1, %2;" : "=l"(d) : "l"(a), "l"(b))
__device__ __forceinline__ u64 pack2(float lo, float hi) {
    u64 d;
    asm("mov.b64 %0, {%1, %2};" : "=l"(d) : "r"(__float_as_uint(lo)), "r"(__float_as_uint(hi)));
    return d;
}
__device__ __forceinline__ void unpack2(u64 v, float& lo, float& hi) {
    uint32_t a, b;
    asm("mov.b64 {%0, %1}, %2;" : "=r"(a), "=r"(b) : "l"(v));
    lo = __uint_as_float(a); hi = __uint_as_float(b);
}
__device__ __forceinline__ float ex2a(float x) {
    float r;
    asm("ex2.approx.f32 %0, %1;" : "=f"(r) : "f"(x));
    return r;
}
// ---- cp.async (sm_80 base ISA) ----
__device__ __forceinline__ void cp16(uint32_t saddr, const void* g) {
    asm volatile("cp.async.ca.shared.global [%0], [%1], 16;" :: "r"(saddr), "l"(g) : "memory");
}
#define CP_COMMIT() asm volatile("cp.async.commit_group;" ::: "memory")
#define CP_WAIT(n)  asm volatile("cp.async.wait_group %0;" :: "n"(n) : "memory")

// ============================================================
// Weight concat: g_wf[k][0:2048]=wq[k], [2048:2560]=wk[k], [2560:3072]=wv[k]
// ============================================================
__global__ void concat_w(const float* __restrict__ wq, const float* __restrict__ wk,
                         const float* __restrict__ wv, float* __restrict__ out)
{
    int i = blockIdx.x * 256 + threadIdx.x;          // one float4 each
    const int ntot = DIMV * (QKVW / 4);
    if (i >= ntot) return;
    int row = i / (QKVW / 4);
    int col = (i - row * (QKVW / 4)) * 4;
    float4 v;
    if (col < DIMV)
        v = *(const float4*)(wq + (size_t)row * DIMV + col);
    else if (col < DIMV + KVDIM)
        v = *(const float4*)(wk + (size_t)row * KVDIM + (col - DIMV));
    else
        v = *(const float4*)(wv + (size_t)row * KVDIM + (col - DIMV - KVDIM));
    *(float4*)(out + (size_t)row * QKVW + col) = v;
}

// ============================================================
// TF32 tensor-core GEMM (proven in R3): C[M,N] = A[M,K] @ B[K,N].
// BM=BN=128, BK=16, 256 threads (8 warps 4x2), warp tile 32x64.
// ============================================================
#define BM 128
#define BN 128
#define BK 16
#define ASTR 20

__device__ __forceinline__ uint32_t f2tf32(float x) {
    uint32_t u;
    asm("cvt.rna.tf32.f32 %0, %1;" : "=r"(u) : "f"(x));
    return u;
}
__device__ __forceinline__ void mma_tf32(float* d, const uint32_t* a, const uint32_t* b) {
    asm volatile(
        "mma.sync.aligned.m16n8k8.row.col.f32.tf32.tf32.f32 "
        "{%0,%1,%2,%3}, {%4,%5,%6,%7}, {%8,%9}, {%0,%1,%2,%3};\n"
        : "+f"(d[0]), "+f"(d[1]), "+f"(d[2]), "+f"(d[3])
        : "r"(a[0]), "r"(a[1]), "r"(a[2]), "r"(a[3]),
          "r"(b[0]), "r"(b[1]));
}

__global__ __launch_bounds__(256) void tgemm_kernel(
    const float* __restrict__ A, const float* __restrict__ B,
    float* __restrict__ C, int M, int N, int K)
{
    __shared__ uint32_t As[2][BM * ASTR];
    __shared__ uint32_t Bs[2][BK * BN];

    const int tid  = threadIdx.x;
    const int wid  = tid >> 5;
    const int lane = tid & 31;
    const int g    = lane >> 2;
    const int t    = lane & 3;
    const int m0   = blockIdx.y * BM;
    const int n0   = blockIdx.x * BN;
    const int mrow = (wid & 3) * 32;
    const int ncol = (wid >> 2) * 64;

    const int ar0 = tid >> 2,          ac0 = (tid & 3) * 4;
    const int ar1 = (tid + 256) >> 2,  ac1 = ((tid + 256) & 3) * 4;
    const int br0 = tid >> 5,          bn0 = (tid & 31) * 4;
    const int br1 = (tid + 256) >> 5,  bn1 = bn0;
    const int bs0 = bn0 ^ (8 * (br0 & 3));
    const int bs1 = bn1 ^ (8 * (br1 & 3));

    const float* Ag0 = A + (size_t)(m0 + ar0) * K + ac0;
    const float* Ag1 = A + (size_t)(m0 + ar1) * K + ac1;
    const float* Bg0 = B + (size_t)br0 * N + n0 + bn0;
    const float* Bg1 = B + (size_t)br1 * N + n0 + bn1;

    float acc[2][8][4];
#pragma unroll
    for (int mt = 0; mt < 2; mt++)
#pragma unroll
        for (int nt = 0; nt < 8; nt++)
#pragma unroll
            for (int r = 0; r < 4; r++) acc[mt][nt][r] = 0.f;

    {
        float4 a0 = *(const float4*)(Ag0);
        float4 a1 = *(const float4*)(Ag1);
        float4 b0 = *(const float4*)(Bg0);
        float4 b1 = *(const float4*)(Bg1);
        uint32_t* Asm = As[0];
        Asm[ar0*ASTR + ac0+0] = f2tf32(a0.x); Asm[ar0*ASTR + ac0+1] = f2tf32(a0.y);
        Asm[ar0*ASTR + ac0+2] = f2tf32(a0.z); Asm[ar0*ASTR + ac0+3] = f2tf32(a0.w);
        Asm[ar1*ASTR + ac1+0] = f2tf32(a1.x); Asm[ar1*ASTR + ac1+1] = f2tf32(a1.y);
        Asm[ar1*ASTR + ac1+2] = f2tf32(a1.z); Asm[ar1*ASTR + ac1+3] = f2tf32(a1.w);
        uint32_t* Bsm = Bs[0];
        uint4 bb0 = make_uint4(f2tf32(b0.x), f2tf32(b0.y), f2tf32(b0.z), f2tf32(b0.w));
        uint4 bb1 = make_uint4(f2tf32(b1.x), f2tf32(b1.y), f2tf32(b1.z), f2tf32(b1.w));
        *(uint4*)(&Bsm[br0*BN + bs0]) = bb0;
        *(uint4*)(&Bsm[br1*BN + bs1]) = bb1;
    }
    __syncthreads();

    const int niter = K / BK;
    for (int it = 0; it < niter; it++) {
        const int cur = it & 1, nxt = cur ^ 1;

        float4 pa0, pa1, pb0, pb1;
        const bool has_next = (it + 1) < niter;
        if (has_next) {
            const int ko = (it + 1) * BK;
            pa0 = *(const float4*)(Ag0 + ko);
            pa1 = *(const float4*)(Ag1 + ko);
            pb0 = *(const float4*)(Bg0 + (size_t)ko * N);
            pb1 = *(const float4*)(Bg1 + (size_t)ko * N);
        }

        const uint32_t* Asm = As[cur];
        const uint32_t* Bsm = Bs[cur];
#pragma unroll
        for (int s = 0; s < 2; s++) {
            const int k0 = s * 8;
            uint32_t afr[2][4];
#pragma unroll
            for (int mt = 0; mt < 2; mt++) {
                const int rb = mrow + mt * 16;
                afr[mt][0] = Asm[(rb + g    ) * ASTR + k0 + t    ];
                afr[mt][1] = Asm[(rb + g + 8) * ASTR + k0 + t    ];
                afr[mt][2] = Asm[(rb + g    ) * ASTR + k0 + t + 4];
                afr[mt][3] = Asm[(rb + g + 8) * ASTR + k0 + t + 4];
            }
            uint32_t bfr[8][2];
            const int swz = 8 * t;
#pragma unroll
            for (int nt = 0; nt < 8; nt++) {
                const int col = (ncol + nt * 8 + g) ^ swz;
                bfr[nt][0] = Bsm[(k0 + t    ) * BN + col];
                bfr[nt][1] = Bsm[(k0 + t + 4) * BN + col];
            }
#pragma unroll
            for (int mt = 0; mt < 2; mt++)
#pragma unroll
                for (int nt = 0; nt < 8; nt++)
                    mma_tf32(acc[mt][nt], afr[mt], bfr[nt]);
        }

        if (has_next) {
            uint32_t* Asn = As[nxt];
            Asn[ar0*ASTR + ac0+0] = f2tf32(pa0.x); Asn[ar0*ASTR + ac0+1] = f2tf32(pa0.y);
            Asn[ar0*ASTR + ac0+2] = f2tf32(pa0.z); Asn[ar0*ASTR + ac0+3] = f2tf32(pa0.w);
            Asn[ar1*ASTR + ac1+0] = f2tf32(pa1.x); Asn[ar1*ASTR + ac1+1] = f2tf32(pa1.y);
            Asn[ar1*ASTR + ac1+2] = f2tf32(pa1.z); Asn[ar1*ASTR + ac1+3] = f2tf32(pa1.w);
            uint32_t* Bsn = Bs[nxt];
            uint4 bb0 = make_uint4(f2tf32(pb0.x), f2tf32(pb0.y), f2tf32(pb0.z), f2tf32(pb0.w));
            uint4 bb1 = make_uint4(f2tf32(pb1.x), f2tf32(pb1.y), f2tf32(pb1.z), f2tf32(pb1.w));
            *(uint4*)(&Bsn[br0*BN + bs0]) = bb0;
            *(uint4*)(&Bsn[br1*BN + bs1]) = bb1;
            __syncthreads();
        }
    }

#pragma unroll
    for (int mt = 0; mt < 2; mt++) {
#pragma unroll
        for (int nt = 0; nt < 8; nt++) {
            const int row = m0 + mrow + mt * 16 + g;
            const int col = n0 + ncol + nt * 8 + 2 * t;
            float2 lo = make_float2(acc[mt][nt][0], acc[mt][nt][1]);
            float2 hi = make_float2(acc[mt][nt][2], acc[mt][nt][3]);
            *(float2*)(C + (size_t)row * N + col)       = lo;
            *(float2*)(C + (size_t)(row + 8) * N + col) = hi;
        }
    }
}

// ============================================================
// RoPE, single launch covering q segment then k segment of g_qkv.
// idx < NPQ -> q pair (width 2048); else k pair (width 512).
// ============================================================
#define NPQ (MROWS * (DIMV / 2))
#define NPK (MROWS * (KVDIM / 2))
__global__ void rope_all_kernel()
{
    int idx = blockIdx.x * blockDim.x + threadIdx.x;
    float* seg;
    int width;
    if (idx < NPQ) {
        seg = g_qkv; width = DIMV;
    } else {
        idx -= NPQ;
        if (idx >= NPK) return;
        seg = g_qkv + DIMV; width = KVDIM;
    }
    int ppr  = width >> 1;
    int row  = idx / ppr;
    int p    = idx - row * ppr;
    int i    = p & 31;
    int col  = ((p >> 5) << 6) + (i << 1);
    int n    = row & (SEQ - 1);

    float freq  = powf(10000.0f, -(float)i * (1.0f / 32.0f));
    float phase = (float)n * freq;
    float s, c;
    sincosf(phase, &s, &c);

    float* base = seg + (size_t)row * QKVW + col;
    float x0 = base[0];
    float x1 = base[1];
    base[0] = x0 * c - x1 * s;
    base[1] = x0 * s + x1 * c;
}

// ============================================================
// Flash attention (causal, GQA rep=4), fp32 packed f32x2 math,
// cp.async double-buffered K/V staging, heaviest-blocks-first.
// grid = (SEQ/128, B*H), block = 128. Thread t owns one query row.
// Addresses for staging are recomputed inline (saves ~36 regs vs
// precomputed pointer arrays -> keeps sv[]/q2/acc2 spill-free).
// ============================================================
__global__ __launch_bounds__(128) void flash_kernel()
{
    __shared__ float4 Ksh[2][32 * 16];   // 2 x (32 keys x 64 floats) = 2 x 8192 B
    __shared__ float4 Vsh[2][32 * 16];

    const int t  = threadIdx.x;
    const int qt = (gridDim.x - 1) - blockIdx.x;   // LPT: heavy blocks first
    const int bh = blockIdx.y;
    const int b  = bh >> 5;
    const int h  = bh & 31;
    const int qi = qt * 128 + t;
    const int kvh = h >> 2;

    const float scale = 0.125f * 1.4426950408889634f;  // 1/sqrt(64) * log2(e)

    // staging bases (scalars only; per-slot addresses recomputed inline)
    const uint32_t ksh_base = (uint32_t)__cvta_generic_to_shared(&Ksh[0][0]);
    const uint32_t vsh_base = (uint32_t)__cvta_generic_to_shared(&Vsh[0][0]);
    // global row base for this thread's KV head (k segment; v = +KVDIM)
    const float* gbaseK = g_qkv + (size_t)(b * SEQ) * QKVW + DIMV + kvh * HD;

    // q row -> 32 packed pairs, pre-scaled
    u64 q2[32];
    const float4* qp = (const float4*)(g_qkv + (size_t)(b * SEQ + qi) * QKVW + h * HD);
#pragma unroll
    for (int dd = 0; dd < 16; dd++) {
        float4 v = qp[dd];
        q2[2*dd]   = pack2(v.x * scale, v.y * scale);
        q2[2*dd+1] = pack2(v.z * scale, v.w * scale);
    }

    float m = -INFINITY, l = 0.f;
    u64 acc2[32];
#pragma unroll
    for (int dd = 0; dd < 32; dd++) acc2[dd] = pack2(0.f, 0.f);

    const int ntiles = qt * 4 + 4;

    // issue tile 0 into buffer 0
#pragma unroll
    for (int u = 0; u < 4; u++) {
        int f  = t + u * 128;
        int j  = f >> 4;
        int dd = f & 15;
        const float* src = gbaseK + (size_t)j * QKVW + dd * 4;
        cp16(ksh_base + f * 16, src);
        cp16(vsh_base + f * 16, src + KVDIM);
    }
    CP_COMMIT();

    for (int kt = 0; kt < ntiles; kt++) {
        const int cur = kt & 1, nxt = cur ^ 1;
        const bool has_next = (kt + 1) < ntiles;

        // issue next tile into other buffer (safe: last read of nxt was at
        // kt-1, followed by the end-of-iteration barrier)
        if (has_next) {
            const uint32_t koff = (uint32_t)nxt * 8192u;
#pragma unroll
            for (int u = 0; u < 4; u++) {
                int f  = t + u * 128;
                int j  = f >> 4;
                int dd = f & 15;
                const float* src = gbaseK + (size_t)((kt + 1) * 32 + j) * QKVW + dd * 4;
                cp16(ksh_base + koff + f * 16, src);
                cp16(vsh_base + koff + f * 16, src + KVDIM);
            }
            CP_COMMIT();
            CP_WAIT(1);          // current tile's group has landed
        } else {
            CP_WAIT(0);
        }
        __syncthreads();

        int jmax = qi - kt * 32 + 1;
        if (jmax > 32) jmax = 32;
        if (jmax > 0) {
            float sv[32];
#pragma unroll
            for (int j = 0; j < 32; j++) {
                u64 s2 = pack2(0.f, 0.f);
                const ulonglong2* kp = (const ulonglong2*)&Ksh[cur][j * 16];
#pragma unroll
                for (int dd = 0; dd < 16; dd++) {
                    ulonglong2 kk = kp[dd];
                    FMA2(s2, q2[2*dd],   kk.x);
                    FMA2(s2, q2[2*dd+1], kk.y);
                }
                float slo, shi;
                unpack2(s2, slo, shi);
                float s = slo + shi;
                sv[j] = (j < jmax) ? s : -INFINITY;
            }
            float tm = -INFINITY;
#pragma unroll
            for (int j = 0; j < 32; j++) tm = fmaxf(tm, sv[j]);
            float nm   = fmaxf(m, tm);
            float corr = ex2a(m - nm);          // m=-inf first tile -> 0
            l *= corr;
            u64 corr2 = pack2(corr, corr);
#pragma unroll
            for (int dd = 0; dd < 32; dd++) MUL2(acc2[dd], acc2[dd], corr2);
#pragma unroll
            for (int j = 0; j < 32; j++) {
                float p = ex2a(sv[j] - nm);     // masked -> 0
                l += p;
                u64 p2 = pack2(p, p);
                const ulonglong2* vp = (const ulonglong2*)&Vsh[cur][j * 16];
#pragma unroll
                for (int dd = 0; dd < 16; dd++) {
                    ulonglong2 vvp = vp[dd];
                    FMA2(acc2[2*dd],   p2, vvp.x);
                    FMA2(acc2[2*dd+1], p2, vvp.y);
                }
            }
            m = nm;
        }
        __syncthreads();
    }

    float inv = 1.0f / l;
    float4* op = (float4*)(g_attn + (size_t)(b * SEQ + qi) * DIMV + h * HD);
#pragma unroll
    for (int dd = 0; dd < 16; dd++) {
        float a, bf, c, d;
        unpack2(acc2[2*dd],   a, bf);
        unpack2(acc2[2*dd+1], c, d);
        op[dd] = make_float4(a * inv, bf * inv, c * inv, d * inv);
    }
}

// ============================================================
// Launch
// ============================================================
extern "C" void kernel_launch(void* const* d_in, const int* in_sizes, int n_in,
                              void* d_out, int out_size)
{
    const float* x  = (const float*)d_in[0];
    const float* wq = (const float*)d_in[1];
    const float* wk = (const float*)d_in[2];
    const float* wv = (const float*)d_in[3];
    const float* wo = (const float*)d_in[4];
    float* out = (float*)d_out;

    float *pqkv, *pa, *pwf;
    cudaGetSymbolAddress((void**)&pqkv, g_qkv);
    cudaGetSymbolAddress((void**)&pa, g_attn);
    cudaGetSymbolAddress((void**)&pwf, g_wf);

    // 1) fuse weights [wq|wk|wv] -> g_wf [2048][3072]
    {
        int ntot = DIMV * (QKVW / 4);
        concat_w<<<(ntot + 255) / 256, 256>>>(wq, wk, wv, pwf);
    }

    // 2) fused qkv projection: g_qkv = x @ g_wf   [2048 x 3072]
    tgemm_kernel<<<dim3(QKVW / BN, MROWS / BM), 256>>>(x, pwf, pqkv, MROWS, QKVW, DIMV);

    // 3) RoPE on q and k segments (single launch, in place)
    {
        int ntot = NPQ + NPK;
        rope_all_kernel<<<(ntot + 255) / 256, 256>>>();
    }

    // 4) causal GQA attention -> g_attn
    flash_kernel<<<dim3(SEQ / 128, BATCH * NHEADS), dim3(128)>>>();

    // 5) out = attn @ wo
    tgemm_kernel<<<dim3(DIMV / BN, MROWS / BM), 256>>>(pa, wo, out, MROWS, DIMV, DIMV);
}